// round 3
// baseline (speedup 1.0000x reference)
#include <cuda_runtime.h>
#include <cuda_bf16.h>
#include <cstdint>

// ---------------------------------------------------------------------------
// B=8192, D=256.
// loss = -sum_ij log_sigmoid(y_ij * (che_i . loc_j * exp(t') + b)) / B
// y = +1 diag, -1 off-diag.
//
// NOTE: harness PTX target is compute_103 (no 'a') -> tcgen05 unavailable.
// Use mma.sync m16n8k16 bf16 (portable PTX) instead.
// ---------------------------------------------------------------------------

#define BATCH 8192
#define DIM   256
#define TM    128
#define TN    128

// SMEM row stride: 256 bf16 + 8 pad -> 264 elems = 528 bytes (conflict-free
// ldmatrix: 8 rows apart by 528B hit bank offsets 4*r, distinct mod 32).
#define LDS_STRIDE 264
#define TILE_BYTES (TM * LDS_STRIDE * 2)     // 67584
#define SMEM_TOTAL (2 * TILE_BYTES)          // 135168

// Scratch (device globals; no allocation allowed)
__device__ __nv_bfloat16 g_che[BATCH * DIM];
__device__ __nv_bfloat16 g_loc[BATCH * DIM];
__device__ float g_scale;
__device__ float g_shift;
__device__ float g_acc;

__device__ __forceinline__ uint32_t smem_u32(const void* p) {
    uint32_t a;
    asm("{ .reg .u64 t; cvta.to.shared.u64 t, %1; cvt.u32.u64 %0, t; }"
        : "=r"(a) : "l"(p));
    return a;
}

__device__ __forceinline__ void ldmatrix_x4(uint32_t* r, uint32_t addr) {
    asm volatile("ldmatrix.sync.aligned.m8n8.x4.shared.b16 {%0,%1,%2,%3}, [%4];"
                 : "=r"(r[0]), "=r"(r[1]), "=r"(r[2]), "=r"(r[3])
                 : "r"(addr));
}

__device__ __forceinline__ void mma_bf16(float* c, const uint32_t* a,
                                         uint32_t b0, uint32_t b1) {
    asm volatile(
        "mma.sync.aligned.m16n8k16.row.col.f32.bf16.bf16.f32 "
        "{%0,%1,%2,%3}, {%4,%5,%6,%7}, {%8,%9}, {%0,%1,%2,%3};"
        : "+f"(c[0]), "+f"(c[1]), "+f"(c[2]), "+f"(c[3])
        : "r"(a[0]), "r"(a[1]), "r"(a[2]), "r"(a[3]), "r"(b0), "r"(b1));
}

// ---------------------------------------------------------------------------
// Kernel 1: row L2-normalize both matrices -> bf16 scratch; scalars
// ---------------------------------------------------------------------------
__global__ void norm_kernel(const float* __restrict__ loc,
                            const float* __restrict__ che,
                            const float* __restrict__ t_prime,
                            const float* __restrict__ b_in)
{
    int row = blockIdx.x;
    int t = threadIdx.x;
    float v0 = loc[row * DIM + t];
    float v1 = che[row * DIM + t];
    float s0 = v0 * v0, s1 = v1 * v1;
    #pragma unroll
    for (int o = 16; o > 0; o >>= 1) {
        s0 += __shfl_xor_sync(0xFFFFFFFFu, s0, o);
        s1 += __shfl_xor_sync(0xFFFFFFFFu, s1, o);
    }
    __shared__ float sh0[8], sh1[8];
    int w = t >> 5, l = t & 31;
    if (l == 0) { sh0[w] = s0; sh1[w] = s1; }
    __syncthreads();
    if (t == 0) {
        float a = 0.f, bb = 0.f;
        #pragma unroll
        for (int i = 0; i < 8; i++) { a += sh0[i]; bb += sh1[i]; }
        sh0[0] = rsqrtf(a);
        sh1[0] = rsqrtf(bb);
    }
    __syncthreads();
    g_loc[row * DIM + t] = __float2bfloat16(v0 * sh0[0]);
    g_che[row * DIM + t] = __float2bfloat16(v1 * sh1[0]);
    if (row == 0 && t == 0) {
        g_scale = expf(t_prime[0]);
        g_shift = b_in[0];
        g_acc = 0.0f;
    }
}

// ---------------------------------------------------------------------------
// Kernel 2: 128x128-tile GEMM (mma.sync bf16) + fused softplus epilogue.
// 8 warps: warp w -> M-rows [ (w&3)*32, +32 ), N-cols [ (w>>2)*64, +64 ).
// Per warp: 2 (M16) x 8 (N8) mma tiles, K=256 in 16 k-steps.
// ---------------------------------------------------------------------------
__global__ __launch_bounds__(256, 1)
void gemm_loss_kernel()
{
    extern __shared__ __align__(16) char smem[];
    const uint32_t sA = smem_u32(smem);
    const uint32_t sB = sA + TILE_BYTES;

    int tid = threadIdx.x;
    int wid = tid >> 5;
    int lane = tid & 31;

    int m0 = blockIdx.y * TM;
    int n0 = blockIdx.x * TN;

    // ---- load tiles: A = che rows [m0,+128), B = loc rows [n0,+128) ----
    const uint4* cheq = reinterpret_cast<const uint4*>(g_che);
    const uint4* locq = reinterpret_cast<const uint4*>(g_loc);
    #pragma unroll
    for (int it = 0; it < 16; it++) {
        int idx = it * 256 + tid;           // 0..4095
        int r = idx >> 5;                   // tile row
        int c = idx & 31;                   // 16B chunk (8 bf16)
        uint32_t off = (uint32_t)(r * (LDS_STRIDE * 2) + c * 16);
        *reinterpret_cast<uint4*>(smem + off) = cheq[(m0 + r) * 32 + c];
        *reinterpret_cast<uint4*>(smem + TILE_BYTES + off) = locq[(n0 + r) * 32 + c];
    }
    __syncthreads();

    // ---- per-thread ldmatrix base addresses ----
    // A (m16k16 x4): row = am + (lane & 15), col elem = (lane>>4)*8
    // B (two n8k16 via x4): row = bn + ((lane>>4)<<3) + (lane&7),
    //                       col elem = ((lane>>3)&1)*8
    int am = (wid & 3) * 32;
    int bn = (wid >> 2) * 64;

    uint32_t aBase0 = sA + (uint32_t)((am + (lane & 15)) * (LDS_STRIDE * 2)
                                      + ((lane >> 4) << 3) * 2);
    uint32_t aBase1 = aBase0 + 16u * (LDS_STRIDE * 2);

    uint32_t bRowPart = (uint32_t)(((lane >> 4) << 3) + (lane & 7));
    uint32_t bColPart = (uint32_t)((((lane >> 3) & 1) << 3) * 2);
    uint32_t bBase[4];
    #pragma unroll
    for (int q = 0; q < 4; q++)
        bBase[q] = sB + (uint32_t)((bn + q * 16 + bRowPart) * (LDS_STRIDE * 2)) + bColPart;

    float c[16][4];
    #pragma unroll
    for (int i = 0; i < 16; i++)
        #pragma unroll
        for (int j = 0; j < 4; j++) c[i][j] = 0.0f;

    #pragma unroll
    for (int ks = 0; ks < 16; ks++) {
        uint32_t koff = (uint32_t)(ks * 32);   // 16 bf16 = 32 bytes
        uint32_t a0[4], a1[4], b[4][4];
        ldmatrix_x4(a0, aBase0 + koff);
        ldmatrix_x4(a1, aBase1 + koff);
        #pragma unroll
        for (int q = 0; q < 4; q++) ldmatrix_x4(b[q], bBase[q] + koff);

        #pragma unroll
        for (int nt = 0; nt < 8; nt++) {
            uint32_t b0 = b[nt >> 1][(nt & 1) ? 2 : 0];
            uint32_t b1 = b[nt >> 1][(nt & 1) ? 3 : 1];
            mma_bf16(c[nt],     a0, b0, b1);
            mma_bf16(c[8 + nt], a1, b0, b1);
        }
    }

    // ---- fused epilogue: loss element per accumulator ----
    float scale = g_scale;
    float shift = g_shift;
    float acc = 0.0f;

    int rbase = m0 + am + (lane >> 2);          // + mt*16 (+8 for c2/c3)
    int cbase = n0 + bn + (lane & 3) * 2;       // + nt*8 (+1 for odd reg)

    #pragma unroll
    for (int mt = 0; mt < 2; mt++) {
        #pragma unroll
        for (int nt = 0; nt < 8; nt++) {
            float* cc = c[mt * 8 + nt];
            int col0 = cbase + nt * 8;
            #pragma unroll
            for (int j = 0; j < 4; j++) {
                int row = rbase + mt * 16 + ((j >> 1) << 3);
                int col = col0 + (j & 1);
                float z = fmaf(cc[j], scale, shift);
                float v = (row == col) ? z : -z;      // y*z
                float av = fabsf(v);
                float e = __expf(-av);
                float l;
                if (e < 0.0625f) {
                    // log1p(e) ≈ e - e^2/2 + e^3/3, |err| <= e^4/4 < 4e-6
                    l = e * fmaf(e, fmaf(e, 0.33333333f, -0.5f), 1.0f);
                } else {
                    l = log1pf(e);                    // near-diagonal only
                }
                acc += fmaxf(-v, 0.0f) + l;           // softplus(-v)
            }
        }
    }

    // ---- block reduce + one atomic per CTA ----
    #pragma unroll
    for (int o = 16; o > 0; o >>= 1)
        acc += __shfl_xor_sync(0xFFFFFFFFu, acc, o);
    __shared__ float shred[8];
    if (lane == 0) shred[wid] = acc;
    __syncthreads();
    if (tid == 0) {
        float s = 0.f;
        #pragma unroll
        for (int i = 0; i < 8; i++) s += shred[i];
        atomicAdd(&g_acc, s);
    }
}

// ---------------------------------------------------------------------------
// g_acc = sum_ij softplus(-y*z) = sum_ij (-log_sigmoid(y*z)) = -sum(loss_matrix)
// loss  = -sum(loss_matrix)/B  = +g_acc/B
// ---------------------------------------------------------------------------
__global__ void finalize_kernel(float* out)
{
    out[0] = g_acc * (1.0f / (float)BATCH);
}

// ---------------------------------------------------------------------------
extern "C" void kernel_launch(void* const* d_in, const int* in_sizes, int n_in,
                              void* d_out, int out_size)
{
    const float* loc = (const float*)d_in[0];
    const float* che = (const float*)d_in[1];
    const float* tp  = (const float*)d_in[2];
    const float* bb  = (const float*)d_in[3];
    float* out = (float*)d_out;

    norm_kernel<<<BATCH, 256>>>(loc, che, tp, bb);

    static bool attr_set = false;
    if (!attr_set) {
        cudaFuncSetAttribute(gemm_loss_kernel,
                             cudaFuncAttributeMaxDynamicSharedMemorySize, SMEM_TOTAL);
        attr_set = true;
    }
    dim3 grid(BATCH / TN, BATCH / TM);
    gemm_loss_kernel<<<grid, 256, SMEM_TOTAL>>>();

    finalize_kernel<<<1, 1>>>(out);
}

// round 4
// speedup vs baseline: 1.3573x; 1.3573x over previous
#include <cuda_runtime.h>
#include <cuda_bf16.h>
#include <cstdint>

// ---------------------------------------------------------------------------
// B=8192, D=256.
// loss = -sum_ij log_sigmoid(y_ij * (che_i . loc_j * exp(t') + b)) / B
// y = +1 diag, -1 off-diag.
// mma.sync m16n8k16 bf16 path (harness PTX target is compute_103, no tcgen05).
// ---------------------------------------------------------------------------

#define BATCH 8192
#define DIM   256
#define TM    256          // tile M (che rows)
#define TN    128          // tile N (loc rows)

// SMEM row stride: 256 bf16 + 8 pad -> 264 elems = 528 bytes, conflict-free
// for ldmatrix (row step = 132 words -> +4 banks/row, distinct over 8 rows).
#define ROWB 528
#define SMEM_TOTAL ((TM + TN) * ROWB)        // 384*528 = 202752

// Scratch (device globals; no allocation allowed)
__device__ __nv_bfloat16 g_che[BATCH * DIM];
__device__ __nv_bfloat16 g_loc[BATCH * DIM];
__device__ float g_scale;
__device__ float g_shift;
__device__ float g_acc;

__device__ __forceinline__ uint32_t smem_u32(const void* p) {
    uint32_t a;
    asm("{ .reg .u64 t; cvta.to.shared.u64 t, %1; cvt.u32.u64 %0, t; }"
        : "=r"(a) : "l"(p));
    return a;
}

__device__ __forceinline__ void ldmatrix_x4(uint32_t* r, uint32_t addr) {
    asm volatile("ldmatrix.sync.aligned.m8n8.x4.shared.b16 {%0,%1,%2,%3}, [%4];"
                 : "=r"(r[0]), "=r"(r[1]), "=r"(r[2]), "=r"(r[3])
                 : "r"(addr));
}

__device__ __forceinline__ void mma_bf16(float* c, const uint32_t* a,
                                         uint32_t b0, uint32_t b1) {
    asm volatile(
        "mma.sync.aligned.m16n8k16.row.col.f32.bf16.bf16.f32 "
        "{%0,%1,%2,%3}, {%4,%5,%6,%7}, {%8,%9}, {%0,%1,%2,%3};"
        : "+f"(c[0]), "+f"(c[1]), "+f"(c[2]), "+f"(c[3])
        : "r"(a[0]), "r"(a[1]), "r"(a[2]), "r"(a[3]), "r"(b0), "r"(b1));
}

#define CP_ASYNC16(dst, src) \
    asm volatile("cp.async.cg.shared.global [%0], [%1], 16;" \
                 :: "r"(dst), "l"(src) : "memory")
#define CP_COMMIT() asm volatile("cp.async.commit_group;" ::: "memory")
#define CP_WAIT(n)  asm volatile("cp.async.wait_group %0;" :: "n"(n) : "memory")

// ---------------------------------------------------------------------------
// Kernel 1: row L2-normalize -> bf16 scratch. One warp per row, 8 elem/thread.
// grid = BATCH/8 blocks of 256 threads (8 warps).
// ---------------------------------------------------------------------------
__global__ __launch_bounds__(256)
void norm_kernel(const float* __restrict__ loc,
                 const float* __restrict__ che,
                 const float* __restrict__ t_prime,
                 const float* __restrict__ b_in)
{
    int row  = (blockIdx.x << 3) + (threadIdx.x >> 5);
    int lane = threadIdx.x & 31;

    const float4* l4 = reinterpret_cast<const float4*>(loc + row * DIM) + lane * 2;
    const float4* c4 = reinterpret_cast<const float4*>(che + row * DIM) + lane * 2;
    float4 a0 = l4[0], a1 = l4[1];
    float4 b0 = c4[0], b1 = c4[1];

    float s0 = a0.x*a0.x + a0.y*a0.y + a0.z*a0.z + a0.w*a0.w
             + a1.x*a1.x + a1.y*a1.y + a1.z*a1.z + a1.w*a1.w;
    float s1 = b0.x*b0.x + b0.y*b0.y + b0.z*b0.z + b0.w*b0.w
             + b1.x*b1.x + b1.y*b1.y + b1.z*b1.z + b1.w*b1.w;
    #pragma unroll
    for (int o = 16; o > 0; o >>= 1) {
        s0 += __shfl_xor_sync(0xFFFFFFFFu, s0, o);
        s1 += __shfl_xor_sync(0xFFFFFFFFu, s1, o);
    }
    float r0 = rsqrtf(s0);
    float r1 = rsqrtf(s1);

    __nv_bfloat162 h[4];
    h[0] = __float22bfloat162_rn(make_float2(a0.x*r0, a0.y*r0));
    h[1] = __float22bfloat162_rn(make_float2(a0.z*r0, a0.w*r0));
    h[2] = __float22bfloat162_rn(make_float2(a1.x*r0, a1.y*r0));
    h[3] = __float22bfloat162_rn(make_float2(a1.z*r0, a1.w*r0));
    *reinterpret_cast<uint4*>(g_loc + row * DIM + lane * 8) =
        *reinterpret_cast<uint4*>(h);

    h[0] = __float22bfloat162_rn(make_float2(b0.x*r1, b0.y*r1));
    h[1] = __float22bfloat162_rn(make_float2(b0.z*r1, b0.w*r1));
    h[2] = __float22bfloat162_rn(make_float2(b1.x*r1, b1.y*r1));
    h[3] = __float22bfloat162_rn(make_float2(b1.z*r1, b1.w*r1));
    *reinterpret_cast<uint4*>(g_che + row * DIM + lane * 8) =
        *reinterpret_cast<uint4*>(h);

    if (blockIdx.x == 0 && threadIdx.x == 0) {
        g_scale = expf(t_prime[0]);
        g_shift = b_in[0];
        g_acc = 0.0f;
    }
}

// ---------------------------------------------------------------------------
// Kernel 2: 256x128-tile GEMM (mma.sync bf16) + fused softplus epilogue.
// 16 warps: warp w -> M-rows [(w>>1)*32, +32), N-cols [(w&1)*64, +64).
// cp.async 2-group K-split pipeline (K[0:128) / K[128:256)).
// ---------------------------------------------------------------------------
__global__ __launch_bounds__(512, 1)
void gemm_loss_kernel()
{
    extern __shared__ __align__(16) char smem[];
    const uint32_t sBase = smem_u32(smem);
    const uint32_t sA = sBase;                 // rows 0..255   : che tile
    const uint32_t sB = sBase + TM * ROWB;     // rows 256..383 : loc tile

    int tid = threadIdx.x;
    int wid = tid >> 5;
    int lane = tid & 31;

    int m0 = blockIdx.y * TM;
    int n0 = blockIdx.x * TN;

    const uint4* cheq = reinterpret_cast<const uint4*>(g_che);
    const uint4* locq = reinterpret_cast<const uint4*>(g_loc);

    // ---- cp.async loads: 384 rows x 32 chunks of 16B, split into 2 K-groups
    // group 0: k-chunks 0..15, group 1: k-chunks 16..31
    #pragma unroll
    for (int it = 0; it < 12; it++) {
        int idx = it * 512 + tid;              // 0..6143
        int r = idx >> 4;
        int c = idx & 15;
        uint32_t dst = sBase + (uint32_t)(r * ROWB + c * 16);
        const uint4* src = (r < TM) ? &cheq[(m0 + r) * 32 + c]
                                    : &locq[(n0 + r - TM) * 32 + c];
        CP_ASYNC16(dst, src);
    }
    CP_COMMIT();
    #pragma unroll
    for (int it = 0; it < 12; it++) {
        int idx = it * 512 + tid;
        int r = idx >> 4;
        int c = (idx & 15) + 16;
        uint32_t dst = sBase + (uint32_t)(r * ROWB + c * 16);
        const uint4* src = (r < TM) ? &cheq[(m0 + r) * 32 + c]
                                    : &locq[(n0 + r - TM) * 32 + c];
        CP_ASYNC16(dst, src);
    }
    CP_COMMIT();

    // ---- per-thread ldmatrix base addresses ----
    int am = (wid >> 1) * 32;
    int bn = (wid & 1) * 64;

    uint32_t aBase0 = sA + (uint32_t)((am + (lane & 15)) * ROWB
                                      + ((lane >> 4) << 3) * 2);
    uint32_t aBase1 = aBase0 + 16u * ROWB;

    uint32_t bRowPart = (uint32_t)(((lane >> 4) << 3) + (lane & 7));
    uint32_t bColPart = (uint32_t)((((lane >> 3) & 1) << 3) * 2);
    uint32_t bBase[4];
    #pragma unroll
    for (int q = 0; q < 4; q++)
        bBase[q] = sB + (uint32_t)((bn + q * 16 + bRowPart) * ROWB) + bColPart;

    float c[16][4];
    #pragma unroll
    for (int i = 0; i < 16; i++)
        #pragma unroll
        for (int j = 0; j < 4; j++) c[i][j] = 0.0f;

    // ---- first K half ----
    CP_WAIT(1);
    __syncthreads();
    #pragma unroll
    for (int ks = 0; ks < 8; ks++) {
        uint32_t koff = (uint32_t)(ks * 32);
        uint32_t a0[4], a1[4], b[4][4];
        ldmatrix_x4(a0, aBase0 + koff);
        ldmatrix_x4(a1, aBase1 + koff);
        #pragma unroll
        for (int q = 0; q < 4; q++) ldmatrix_x4(b[q], bBase[q] + koff);
        #pragma unroll
        for (int nt = 0; nt < 8; nt++) {
            uint32_t b0 = b[nt >> 1][(nt & 1) ? 2 : 0];
            uint32_t b1 = b[nt >> 1][(nt & 1) ? 3 : 1];
            mma_bf16(c[nt],     a0, b0, b1);
            mma_bf16(c[8 + nt], a1, b0, b1);
        }
    }

    // ---- second K half ----
    CP_WAIT(0);
    __syncthreads();
    #pragma unroll
    for (int ks = 8; ks < 16; ks++) {
        uint32_t koff = (uint32_t)(ks * 32);
        uint32_t a0[4], a1[4], b[4][4];
        ldmatrix_x4(a0, aBase0 + koff);
        ldmatrix_x4(a1, aBase1 + koff);
        #pragma unroll
        for (int q = 0; q < 4; q++) ldmatrix_x4(b[q], bBase[q] + koff);
        #pragma unroll
        for (int nt = 0; nt < 8; nt++) {
            uint32_t b0 = b[nt >> 1][(nt & 1) ? 2 : 0];
            uint32_t b1 = b[nt >> 1][(nt & 1) ? 3 : 1];
            mma_bf16(c[nt],     a0, b0, b1);
            mma_bf16(c[8 + nt], a1, b0, b1);
        }
    }

    // ---- fused epilogue ----
    float scale = g_scale;
    float shift = g_shift;
    float acc = 0.0f;

    int rbase = m0 + am + (lane >> 2);
    int cbase = n0 + bn + (lane & 3) * 2;

    #pragma unroll
    for (int mt = 0; mt < 2; mt++) {
        #pragma unroll
        for (int nt = 0; nt < 8; nt++) {
            float* cc = c[mt * 8 + nt];
            int col0 = cbase + nt * 8;
            #pragma unroll
            for (int j = 0; j < 4; j++) {
                int row = rbase + mt * 16 + ((j >> 1) << 3);
                int col = col0 + (j & 1);
                float z = fmaf(cc[j], scale, shift);
                float v = (row == col) ? z : -z;      // y*z
                float av = fabsf(v);
                float e = __expf(-av);
                float l;
                if (e < 0.0625f) {
                    // log1p(e) ~ e - e^2/2 + e^3/3, |err| <= e^4/4 < 4e-6
                    l = e * fmaf(e, fmaf(e, 0.33333333f, -0.5f), 1.0f);
                } else {
                    l = log1pf(e);                    // near-diagonal only
                }
                acc += fmaxf(-v, 0.0f) + l;           // softplus(-v)
            }
        }
    }

    // ---- block reduce + one atomic per CTA ----
    #pragma unroll
    for (int o = 16; o > 0; o >>= 1)
        acc += __shfl_xor_sync(0xFFFFFFFFu, acc, o);
    __shared__ float shred[16];
    if (lane == 0) shred[wid] = acc;
    __syncthreads();
    if (tid == 0) {
        float s = 0.f;
        #pragma unroll
        for (int i = 0; i < 16; i++) s += shred[i];
        atomicAdd(&g_acc, s);
    }
}

// ---------------------------------------------------------------------------
// g_acc = sum_ij -log_sigmoid(y*z)  ->  loss = +g_acc/B
// ---------------------------------------------------------------------------
__global__ void finalize_kernel(float* out)
{
    out[0] = g_acc * (1.0f / (float)BATCH);
}

// ---------------------------------------------------------------------------
extern "C" void kernel_launch(void* const* d_in, const int* in_sizes, int n_in,
                              void* d_out, int out_size)
{
    const float* loc = (const float*)d_in[0];
    const float* che = (const float*)d_in[1];
    const float* tp  = (const float*)d_in[2];
    const float* bb  = (const float*)d_in[3];
    float* out = (float*)d_out;

    norm_kernel<<<BATCH / 8, 256>>>(loc, che, tp, bb);

    static bool attr_set = false;
    if (!attr_set) {
        cudaFuncSetAttribute(gemm_loss_kernel,
                             cudaFuncAttributeMaxDynamicSharedMemorySize, SMEM_TOTAL);
        attr_set = true;
    }
    dim3 grid(BATCH / TN, BATCH / TM);
    gemm_loss_kernel<<<grid, 512, SMEM_TOTAL>>>();

    finalize_kernel<<<1, 1>>>(out);
}